// round 12
// baseline (speedup 1.0000x reference)
#include <cuda_runtime.h>
#include <cuda_bf16.h>
#include <cstdint>

#define BATCH 32
#define SEQ   4096
#define EMBED 512
#define HID   256
#define OUTD  128
#define DECAYF 0.95f
#define LOG2_INV_D 0.07400058144377693f   // log2(1/0.95)

#define KSPLIT (3 * EMBED)                // 1536: A = (hi | hi | lo)

__device__ __nv_bfloat16 g_a3[SEQ * KSPLIT];    // A split   [4096][1536]
__device__ __nv_bfloat16 g_w1t[HID * KSPLIT];   // W1^T split [256][1536]: (hi|lo|hi)
__device__ float    g_curT[HID * SEQ];          // currents TRANSPOSED [256][4096]
__device__ float    g_cnt[HID];
__device__ unsigned g_done;

// ---------------------------------------------------------------------------
// Kernel 1: batch mean (emits split-bf16 A3) + fused W1 split prep.
// ---------------------------------------------------------------------------
__global__ void snn_mean_kernel(const float* __restrict__ x,
                                const float* __restrict__ W1) {
    if (blockIdx.x >= 2048) {                 // --- wprep part ---
        const int k = blockIdx.x - 2048;      // 0..511
        const int n = threadIdx.x;            // 0..255
        float v = W1[(size_t)k * HID + n];
        __nv_bfloat16 hi = __float2bfloat16(v);
        __nv_bfloat16 lo = __float2bfloat16(v - __bfloat162float(hi));
        g_w1t[(size_t)n * KSPLIT + k]             = hi;
        g_w1t[(size_t)n * KSPLIT + EMBED + k]     = lo;
        g_w1t[(size_t)n * KSPLIT + 2 * EMBED + k] = hi;
        return;
    }
    const int NF4 = (SEQ * EMBED) / 4;
    int i = blockIdx.x * blockDim.x + threadIdx.x;
    if (i >= NF4) return;
    const float4* x4 = reinterpret_cast<const float4*>(x);
    float sx = 0.f, sy = 0.f, sz = 0.f, sw = 0.f;
#pragma unroll
    for (int b = 0; b < BATCH; b++) {
        float4 v = x4[(size_t)b * NF4 + i];
        sx += v.x; sy += v.y; sz += v.z; sw += v.w;
    }
    const float inv = 1.0f / 32.0f;
    float v0 = sx * inv, v1 = sy * inv, v2 = sz * inv, v3 = sw * inv;

    __nv_bfloat16 h0 = __float2bfloat16(v0), h1 = __float2bfloat16(v1);
    __nv_bfloat16 h2 = __float2bfloat16(v2), h3 = __float2bfloat16(v3);
    __nv_bfloat16 l0 = __float2bfloat16(v0 - __bfloat162float(h0));
    __nv_bfloat16 l1 = __float2bfloat16(v1 - __bfloat162float(h1));
    __nv_bfloat16 l2 = __float2bfloat16(v2 - __bfloat162float(h2));
    __nv_bfloat16 l3 = __float2bfloat16(v3 - __bfloat162float(h3));

    __nv_bfloat162 ha = {h0, h1}, hb = {h2, h3};
    __nv_bfloat162 la = {l0, l1}, lb = {l2, l3};
    uint2 hu, lu;
    hu.x = *reinterpret_cast<unsigned*>(&ha); hu.y = *reinterpret_cast<unsigned*>(&hb);
    lu.x = *reinterpret_cast<unsigned*>(&la); lu.y = *reinterpret_cast<unsigned*>(&lb);

    const int s = i >> 7, d4 = i & 127;
    const size_t base = (size_t)s * KSPLIT + d4 * 4;
    *reinterpret_cast<uint2*>(&g_a3[base])             = hu;
    *reinterpret_cast<uint2*>(&g_a3[base + EMBED])     = hu;
    *reinterpret_cast<uint2*>(&g_a3[base + 2 * EMBED]) = lu;
}

// ---------------------------------------------------------------------------
// Kernel 2: HMMA bf16 GEMM (validated fragment mapping), MT 128 -> 64 for
// 256 blocks (2/SM). 8 warps = 2(m) x 4(n); warp tile 32x16.
// ---------------------------------------------------------------------------
#define MT 64
#define NT 64
#define KCH 64
#define NCH (KSPLIT / KCH)        // 24
#define APIT 72
#define SA_BYTES (MT * APIT * 2)  // 9216
#define SB_BYTES (NT * APIT * 2)  // 9216
// layout (bytes): A0 @0, A1 @9216, B0 @18432, B1 @27648; total 36864
#define SMB_OFF 18432
#define MMA_SMEM_BYTES 36864

__device__ __forceinline__ void cp16(unsigned dst, const void* src) {
    asm volatile("cp.async.cg.shared.global [%0], [%1], 16;" :: "r"(dst), "l"(src));
}
#define CP_COMMIT() asm volatile("cp.async.commit_group;")
#define CP_WAIT1()  asm volatile("cp.async.wait_group 1;")
#define CP_WAIT0()  asm volatile("cp.async.wait_group 0;")

__device__ __forceinline__ void mma16816(float& d0, float& d1, float& d2, float& d3,
                                         uint32_t a0, uint32_t a1, uint32_t a2, uint32_t a3,
                                         uint32_t b0, uint32_t b1) {
    asm volatile(
        "mma.sync.aligned.m16n8k16.row.col.f32.bf16.bf16.f32 "
        "{%0,%1,%2,%3}, {%4,%5,%6,%7}, {%8,%9}, {%0,%1,%2,%3};"
        : "+f"(d0), "+f"(d1), "+f"(d2), "+f"(d3)
        : "r"(a0), "r"(a1), "r"(a2), "r"(a3), "r"(b0), "r"(b1));
}

__global__ void __launch_bounds__(256, 2)
snn_mma_kernel(void) {
    extern __shared__ char smem[];
    const unsigned sb = (unsigned)__cvta_generic_to_shared(smem);
    __nv_bfloat16* sm16 = reinterpret_cast<__nv_bfloat16*>(smem);

    const int tid  = threadIdx.x;
    const int wid  = tid >> 5;
    const int lane = tid & 31;
    const int g = lane >> 2;
    const int t = lane & 3;
    const int warp_m = wid >> 2;     // 0..1 -> 32 m-rows each
    const int warp_n = wid & 3;      // 0..3 -> 16 n-cols each
    const int s0 = blockIdx.x * MT;
    const int h0 = blockIdx.y * NT;

    auto load_chunk = [&](int c, int buf) {
        const __nv_bfloat16* As = &g_a3[(size_t)s0 * KSPLIT + c * KCH];
        unsigned dA = sb + buf * SA_BYTES;
#pragma unroll
        for (int l = 0; l < 2; l++) {
            int f = tid + l * 256;                 // 0..511
            int r = f >> 3, sg = f & 7;
            cp16(dA + r * (APIT * 2) + sg * 16, As + (size_t)r * KSPLIT + sg * 8);
        }
        const __nv_bfloat16* Bs = &g_w1t[(size_t)h0 * KSPLIT + c * KCH];
        unsigned dB = sb + SMB_OFF + buf * SB_BYTES;
#pragma unroll
        for (int l = 0; l < 2; l++) {
            int f = tid + l * 256;                 // 0..511
            int r = f >> 3, sg = f & 7;
            cp16(dB + r * (APIT * 2) + sg * 16, Bs + (size_t)r * KSPLIT + sg * 8);
        }
        CP_COMMIT();
    };

    float acc[2][2][4];
#pragma unroll
    for (int i = 0; i < 2; i++)
#pragma unroll
        for (int j = 0; j < 2; j++)
#pragma unroll
            for (int r = 0; r < 4; r++) acc[i][j][r] = 0.f;

    load_chunk(0, 0);
    load_chunk(1, 1);

#pragma unroll 1
    for (int c = 0; c < NCH; c++) {
        if (c + 1 < NCH) CP_WAIT1(); else CP_WAIT0();
        __syncthreads();

        const int buf = c & 1;
        const __nv_bfloat16* A = sm16 + buf * (SA_BYTES / 2);
        const __nv_bfloat16* B = sm16 + (SMB_OFF / 2) + buf * (SB_BYTES / 2);

#pragma unroll
        for (int ks = 0; ks < KCH / 16; ks++) {
            const int kb = ks * 16;
            uint32_t af[2][4];
#pragma unroll
            for (int mf = 0; mf < 2; mf++) {
                const int rb = warp_m * 32 + mf * 16;
                af[mf][0] = *reinterpret_cast<const uint32_t*>(&A[(rb + g)     * APIT + kb + t * 2]);
                af[mf][1] = *reinterpret_cast<const uint32_t*>(&A[(rb + g + 8) * APIT + kb + t * 2]);
                af[mf][2] = *reinterpret_cast<const uint32_t*>(&A[(rb + g)     * APIT + kb + t * 2 + 8]);
                af[mf][3] = *reinterpret_cast<const uint32_t*>(&A[(rb + g + 8) * APIT + kb + t * 2 + 8]);
            }
            uint32_t bf[2][2];
#pragma unroll
            for (int nf = 0; nf < 2; nf++) {
                const int nr = warp_n * 16 + nf * 8 + g;
                bf[nf][0] = *reinterpret_cast<const uint32_t*>(&B[nr * APIT + kb + t * 2]);
                bf[nf][1] = *reinterpret_cast<const uint32_t*>(&B[nr * APIT + kb + t * 2 + 8]);
            }
#pragma unroll
            for (int mf = 0; mf < 2; mf++)
#pragma unroll
                for (int nf = 0; nf < 2; nf++)
                    mma16816(acc[mf][nf][0], acc[mf][nf][1], acc[mf][nf][2], acc[mf][nf][3],
                             af[mf][0], af[mf][1], af[mf][2], af[mf][3],
                             bf[nf][0], bf[nf][1]);
        }
        __syncthreads();
        if (c + 2 < NCH) load_chunk(c + 2, buf);
    }

    // Epilogue: stage D transposed [n][m] pitch 68, coalesced f4 stores.
    float* sT = reinterpret_cast<float*>(smem);   // [64][68] = 17408 B
#pragma unroll
    for (int mf = 0; mf < 2; mf++) {
        const int mb = warp_m * 32 + mf * 16;
#pragma unroll
        for (int nf = 0; nf < 2; nf++) {
            const int nb = warp_n * 16 + nf * 8 + t * 2;
            sT[(nb + 0) * 68 + mb + g]     = acc[mf][nf][0];
            sT[(nb + 1) * 68 + mb + g]     = acc[mf][nf][1];
            sT[(nb + 0) * 68 + mb + g + 8] = acc[mf][nf][2];
            sT[(nb + 1) * 68 + mb + g + 8] = acc[mf][nf][3];
        }
    }
    __syncthreads();
#pragma unroll
    for (int l = 0; l < 4; l++) {
        int f    = tid + l * 256;     // 0..1023
        int hrow = f >> 4;            // 0..63
        int seg  = f & 15;            // m f4-seg
        float4 v = *reinterpret_cast<float4*>(&sT[hrow * 68 + seg * 4]);
        *reinterpret_cast<float4*>(
            &g_curT[(size_t)(h0 + hrow) * SEQ + s0 + seg * 4]) = v;
    }
}

// ---------------------------------------------------------------------------
// Kernel 3: two-phase LIF scan (R11-validated algebra), TWO units per block
// -> 128 blocks = one wave. Phase A: warps 0-3 unit0, warps 4-7 unit1
// (32 windows each). Phase B: warp 0 runs unit0's serial chain, warp 4
// unit1's, concurrently. Fused output projection in last block.
// ---------------------------------------------------------------------------
#define USTRIDE (3 * SEQ + 128)                 // floats per unit region
#define SCAN_SMEM_FLOATS (2 * USTRIDE)
#define SCAN_SMEM_BYTES  (SCAN_SMEM_FLOATS * 4) // 99328
#define FULLW 0xffffffffu

__global__ void __launch_bounds__(256, 1)
snn_scan_kernel(const float* __restrict__ W2, float* __restrict__ out) {
    extern __shared__ float ssm[];
    __shared__ unsigned slast;

    const int tid  = threadIdx.x;
    const int lane = tid & 31;
    const int warp = tid >> 5;
    const int uh   = warp >> 2;                 // unit half 0/1
    const int wl   = warp & 3;                  // warp-in-half 0..3
    const int h    = blockIdx.x * 2 + uh;

    float*    sQ   = ssm + uh * USTRIDE;
    float*    sXR  = sQ + SEQ;
    unsigned* sTT  = reinterpret_cast<unsigned*>(sQ + 2 * SEQ);
    float*    sP31 = sQ + 3 * SEQ;

    const float dinv = exp2f((float)lane * LOG2_INV_D);   // d^{-lane}
    const float d31  = exp2f(-31.0f * LOG2_INV_D);        // d^31

    // ===== Phase A: 4 warps x 32 windows per unit =====
#pragma unroll 1
    for (int win = wl; win < SEQ / 32; win += 4) {
        float c = g_curT[(size_t)h * SEQ + win * 32 + lane];
        float p = c * dinv;
#pragma unroll
        for (int off = 1; off < 32; off <<= 1) {
            float v = __shfl_up_sync(FULLW, p, off);
            if (lane >= off) p += v;
        }
        float Q  = p - dinv;
        float pv = __shfl_up_sync(FULLW, p, 1);
        float XR = (lane == 0) ? 0.f : pv;                // P_{lane-1}

        float M0 = Q;
        float M1 = fmaxf(M0, __shfl_down_sync(FULLW, M0, 1));
        float M2 = fmaxf(M1, __shfl_down_sync(FULLW, M1, 2));
        float M3 = fmaxf(M2, __shfl_down_sync(FULLW, M2, 4));
        float M4 = fmaxf(M3, __shfl_down_sync(FULLW, M3, 8));
        float M5 = fmaxf(M4, __shfl_down_sync(FULLW, M4, 16));

        const float X = XR;
        const bool exists = (M5 >= X);
        int pos = lane;
        {
            float mk;
            mk = __shfl_sync(FULLW, M4, pos & 31); if (mk < X) pos += 16;
            mk = __shfl_sync(FULLW, M3, pos & 31); if (mk < X) pos += 8;
            mk = __shfl_sync(FULLW, M2, pos & 31); if (mk < X) pos += 4;
            mk = __shfl_sync(FULLW, M1, pos & 31); if (mk < X) pos += 2;
            mk = __shfl_sync(FULLW, M0, pos & 31); if (mk < X) pos += 1;
        }
        unsigned st;
        if (!exists)         st = (2u << 5) | (unsigned)lane;
        else if (pos <= 28)  st = (1u << 7) | (0u << 5) | (unsigned)(pos + 3);
        else                 st = (1u << 7) | (1u << 5) | (unsigned)(pos - 29);

#pragma unroll
        for (int r = 0; r < 4; r++) {
            unsigned s2 = __shfl_sync(FULLW, st, st & 31);
            if (((st >> 5) & 3u) == 0u)
                st = (((st >> 7) + (s2 >> 7)) << 7) | (s2 & 0x7Fu);
        }

        sQ [win * 32 + lane] = Q;
        sXR[win * 32 + lane] = XR;
        sTT[win * 32 + lane] = st;
        if (lane == 31) sP31[win] = p;
    }
    __syncthreads();

    // ===== Phase B: warps 0 and 4, independent serial chains =====
    if (wl == 0) {
        int   isCarry = 1, o = 0, cnt = 0;
        float X = 0.f;
#pragma unroll 1
        for (int win = 0; win < SEQ / 32; win++) {
            float    Qv  = sQ [win * 32 + lane];
            float    XRv = sXR[win * 32 + lane];
            unsigned Tv  = sTT[win * 32 + lane];
            float    P31 = sP31[win];

            unsigned st;
            if (isCarry) {
                st = __shfl_sync(FULLW, Tv, o);
            } else {
                unsigned ball = __ballot_sync(FULLW, Qv >= X);
                if (!ball) { X = -DECAYF * (d31 * (P31 - X)); continue; }
                int t1 = __ffs(ball) - 1;
                cnt++;
                if (t1 >= 29) { isCarry = 1; o = t1 - 29; continue; }
                st = __shfl_sync(FULLW, Tv, t1 + 3);
            }
            cnt += (int)(st >> 7);
            unsigned term = (st >> 5) & 3u;
            unsigned p5   = st & 31u;
            float xr = __shfl_sync(FULLW, XRv, p5);
            if (term == 1u) { isCarry = 1; o = (int)p5; }
            else            { isCarry = 0; X = -DECAYF * (d31 * (P31 - xr)); }
        }
        if (lane == 0) g_cnt[h] = (float)cnt;
    }
    __syncthreads();
    __threadfence();
    if (tid == 0) slast = atomicAdd(&g_done, 1u);
    __syncthreads();

    if (slast == HID / 2 - 1 && tid < OUTD) {
        __threadfence();
        volatile float* vc = g_cnt;
        float a = 0.f;
#pragma unroll 16
        for (int k = 0; k < HID; k++)
            a += vc[k] * W2[(size_t)k * OUTD + tid];
        a *= (1.0f / (float)SEQ);
#pragma unroll
        for (int b = 0; b < BATCH; b++)
            out[(size_t)b * OUTD + tid] = a;
        __threadfence();
        if (tid == 0) g_done = 0;
    }
}

// ---------------------------------------------------------------------------
extern "C" void kernel_launch(void* const* d_in, const int* in_sizes, int n_in,
                              void* d_out, int out_size) {
    const float* x  = (const float*)d_in[0];   // [32][4096][512]
    const float* w1 = (const float*)d_in[1];   // [512][256]
    const float* w2 = (const float*)d_in[2];   // [256][128]
    float* out = (float*)d_out;                // [32][128]

    cudaFuncSetAttribute(snn_mma_kernel,
                         cudaFuncAttributeMaxDynamicSharedMemorySize,
                         MMA_SMEM_BYTES);
    cudaFuncSetAttribute(snn_scan_kernel,
                         cudaFuncAttributeMaxDynamicSharedMemorySize,
                         SCAN_SMEM_BYTES);

    snn_mean_kernel<<<2048 + EMBED, 256>>>(x, w1);
    snn_mma_kernel<<<dim3(SEQ / MT, HID / NT), 256, MMA_SMEM_BYTES>>>();
    snn_scan_kernel<<<HID / 2, 256, SCAN_SMEM_BYTES>>>(w2, out);
}

// round 13
// speedup vs baseline: 1.0406x; 1.0406x over previous
#include <cuda_runtime.h>
#include <cuda_bf16.h>
#include <cstdint>

#define BATCH 32
#define SEQ   4096
#define EMBED 512
#define HID   256
#define OUTD  128
#define DECAYF 0.95f
#define LOG2_INV_D 0.07400058144377693f   // log2(1/0.95)

#define KSPLIT (3 * EMBED)                // 1536: A = (hi | hi | lo)

__device__ __nv_bfloat16 g_a3[SEQ * KSPLIT];    // A split   [4096][1536]
__device__ __nv_bfloat16 g_w1t[HID * KSPLIT];   // W1^T split [256][1536]: (hi|lo|hi)
__device__ float    g_curT[HID * SEQ];          // currents TRANSPOSED [256][4096]
__device__ float    g_cnt[HID];
__device__ unsigned g_done;

// ---------------------------------------------------------------------------
// Kernel 0: W1 split prep (separate tiny kernel; keeps mean kernel lean).
// ---------------------------------------------------------------------------
__global__ void snn_wprep_kernel(const float* __restrict__ W1) {
    const int k = blockIdx.x;        // 512
    const int n = threadIdx.x;       // 256
    float v = W1[(size_t)k * HID + n];
    __nv_bfloat16 hi = __float2bfloat16(v);
    __nv_bfloat16 lo = __float2bfloat16(v - __bfloat162float(hi));
    g_w1t[(size_t)n * KSPLIT + k]             = hi;
    g_w1t[(size_t)n * KSPLIT + EMBED + k]     = lo;
    g_w1t[(size_t)n * KSPLIT + 2 * EMBED + k] = hi;
}

// ---------------------------------------------------------------------------
// Kernel 1: batch mean, emits split-bf16 A3 (hi | hi | lo).
// ---------------------------------------------------------------------------
__global__ void snn_mean_kernel(const float* __restrict__ x) {
    const int NF4 = (SEQ * EMBED) / 4;
    int i = blockIdx.x * blockDim.x + threadIdx.x;
    if (i >= NF4) return;
    const float4* x4 = reinterpret_cast<const float4*>(x);
    float sx = 0.f, sy = 0.f, sz = 0.f, sw = 0.f;
#pragma unroll
    for (int b = 0; b < BATCH; b++) {
        float4 v = x4[(size_t)b * NF4 + i];
        sx += v.x; sy += v.y; sz += v.z; sw += v.w;
    }
    const float inv = 1.0f / 32.0f;
    float v0 = sx * inv, v1 = sy * inv, v2 = sz * inv, v3 = sw * inv;

    __nv_bfloat16 h0 = __float2bfloat16(v0), h1 = __float2bfloat16(v1);
    __nv_bfloat16 h2 = __float2bfloat16(v2), h3 = __float2bfloat16(v3);
    __nv_bfloat16 l0 = __float2bfloat16(v0 - __bfloat162float(h0));
    __nv_bfloat16 l1 = __float2bfloat16(v1 - __bfloat162float(h1));
    __nv_bfloat16 l2 = __float2bfloat16(v2 - __bfloat162float(h2));
    __nv_bfloat16 l3 = __float2bfloat16(v3 - __bfloat162float(h3));

    __nv_bfloat162 ha = {h0, h1}, hb = {h2, h3};
    __nv_bfloat162 la = {l0, l1}, lb = {l2, l3};
    uint2 hu, lu;
    hu.x = *reinterpret_cast<unsigned*>(&ha); hu.y = *reinterpret_cast<unsigned*>(&hb);
    lu.x = *reinterpret_cast<unsigned*>(&la); lu.y = *reinterpret_cast<unsigned*>(&lb);

    const int s = i >> 7, d4 = i & 127;
    const size_t base = (size_t)s * KSPLIT + d4 * 4;
    *reinterpret_cast<uint2*>(&g_a3[base])             = hu;
    *reinterpret_cast<uint2*>(&g_a3[base + EMBED])     = hu;
    *reinterpret_cast<uint2*>(&g_a3[base + 2 * EMBED]) = lu;
}

// ---------------------------------------------------------------------------
// Kernel 2: HMMA bf16 GEMM. MT=128, NT=32 -> grid (32,8)=256 blocks (all SMs
// busy). 8 warps = 4(m) x 2(n); warp tile 32x16. Fragment mapping identical
// to the validated R10/R11 scheme. cp.async double-buffered, wait_group 1.
// ---------------------------------------------------------------------------
#define MT 128
#define NT 32
#define KCH 64
#define NCH (KSPLIT / KCH)        // 24
#define APIT 72
#define SA_BYTES (MT * APIT * 2)  // 18432
#define SB_BYTES (NT * APIT * 2)  // 4608
// layout (bytes): A0 @0, A1 @18432, B0 @36864, B1 @41472; total 46080
#define SMB_OFF 36864
#define MMA_SMEM_BYTES 46080

__device__ __forceinline__ void cp16(unsigned dst, const void* src) {
    asm volatile("cp.async.cg.shared.global [%0], [%1], 16;" :: "r"(dst), "l"(src));
}
#define CP_COMMIT() asm volatile("cp.async.commit_group;")
#define CP_WAIT1()  asm volatile("cp.async.wait_group 1;")
#define CP_WAIT0()  asm volatile("cp.async.wait_group 0;")

__device__ __forceinline__ void mma16816(float& d0, float& d1, float& d2, float& d3,
                                         uint32_t a0, uint32_t a1, uint32_t a2, uint32_t a3,
                                         uint32_t b0, uint32_t b1) {
    asm volatile(
        "mma.sync.aligned.m16n8k16.row.col.f32.bf16.bf16.f32 "
        "{%0,%1,%2,%3}, {%4,%5,%6,%7}, {%8,%9}, {%0,%1,%2,%3};"
        : "+f"(d0), "+f"(d1), "+f"(d2), "+f"(d3)
        : "r"(a0), "r"(a1), "r"(a2), "r"(a3), "r"(b0), "r"(b1));
}

__global__ void __launch_bounds__(256, 1)
snn_mma_kernel(void) {
    extern __shared__ char smem[];
    const unsigned sb = (unsigned)__cvta_generic_to_shared(smem);
    __nv_bfloat16* sm16 = reinterpret_cast<__nv_bfloat16*>(smem);

    const int tid  = threadIdx.x;
    const int wid  = tid >> 5;
    const int lane = tid & 31;
    const int g = lane >> 2;
    const int t = lane & 3;
    const int warp_m = wid >> 1;     // 0..3 -> 32 m-rows each
    const int warp_n = wid & 1;      // 0..1 -> 16 n-cols each
    const int s0 = blockIdx.x * MT;
    const int h0 = blockIdx.y * NT;

    auto load_chunk = [&](int c, int buf) {
        const __nv_bfloat16* As = &g_a3[(size_t)s0 * KSPLIT + c * KCH];
        unsigned dA = sb + buf * SA_BYTES;
#pragma unroll
        for (int l = 0; l < 4; l++) {
            int f = tid + l * 256;                 // 0..1023
            int r = f >> 3, sg = f & 7;
            cp16(dA + r * (APIT * 2) + sg * 16, As + (size_t)r * KSPLIT + sg * 8);
        }
        const __nv_bfloat16* Bs = &g_w1t[(size_t)h0 * KSPLIT + c * KCH];
        unsigned dB = sb + SMB_OFF + buf * SB_BYTES;
        {
            int f = tid;                           // 0..255 (32 rows x 8 segs)
            int r = f >> 3, sg = f & 7;
            cp16(dB + r * (APIT * 2) + sg * 16, Bs + (size_t)r * KSPLIT + sg * 8);
        }
        CP_COMMIT();
    };

    float acc[2][2][4];
#pragma unroll
    for (int i = 0; i < 2; i++)
#pragma unroll
        for (int j = 0; j < 2; j++)
#pragma unroll
            for (int r = 0; r < 4; r++) acc[i][j][r] = 0.f;

    load_chunk(0, 0);
    load_chunk(1, 1);

#pragma unroll 1
    for (int c = 0; c < NCH; c++) {
        if (c + 1 < NCH) CP_WAIT1(); else CP_WAIT0();
        __syncthreads();

        const int buf = c & 1;
        const __nv_bfloat16* A = sm16 + buf * (SA_BYTES / 2);
        const __nv_bfloat16* B = sm16 + (SMB_OFF / 2) + buf * (SB_BYTES / 2);

#pragma unroll
        for (int ks = 0; ks < KCH / 16; ks++) {
            const int kb = ks * 16;
            uint32_t af[2][4];
#pragma unroll
            for (int mf = 0; mf < 2; mf++) {
                const int rb = warp_m * 32 + mf * 16;
                af[mf][0] = *reinterpret_cast<const uint32_t*>(&A[(rb + g)     * APIT + kb + t * 2]);
                af[mf][1] = *reinterpret_cast<const uint32_t*>(&A[(rb + g + 8) * APIT + kb + t * 2]);
                af[mf][2] = *reinterpret_cast<const uint32_t*>(&A[(rb + g)     * APIT + kb + t * 2 + 8]);
                af[mf][3] = *reinterpret_cast<const uint32_t*>(&A[(rb + g + 8) * APIT + kb + t * 2 + 8]);
            }
            uint32_t bf[2][2];
#pragma unroll
            for (int nf = 0; nf < 2; nf++) {
                const int nr = warp_n * 16 + nf * 8 + g;
                bf[nf][0] = *reinterpret_cast<const uint32_t*>(&B[nr * APIT + kb + t * 2]);
                bf[nf][1] = *reinterpret_cast<const uint32_t*>(&B[nr * APIT + kb + t * 2 + 8]);
            }
#pragma unroll
            for (int mf = 0; mf < 2; mf++)
#pragma unroll
                for (int nf = 0; nf < 2; nf++)
                    mma16816(acc[mf][nf][0], acc[mf][nf][1], acc[mf][nf][2], acc[mf][nf][3],
                             af[mf][0], af[mf][1], af[mf][2], af[mf][3],
                             bf[nf][0], bf[nf][1]);
        }
        __syncthreads();
        if (c + 2 < NCH) load_chunk(c + 2, buf);
    }

    // Epilogue: stage D transposed [n][m] (pitch 132), coalesced f4 stores.
    float* sT = reinterpret_cast<float*>(smem);   // [32][132] = 16896 B
#pragma unroll
    for (int mf = 0; mf < 2; mf++) {
        const int mb = warp_m * 32 + mf * 16;
#pragma unroll
        for (int nf = 0; nf < 2; nf++) {
            const int nb = warp_n * 16 + nf * 8 + t * 2;
            sT[(nb + 0) * 132 + mb + g]     = acc[mf][nf][0];
            sT[(nb + 1) * 132 + mb + g]     = acc[mf][nf][1];
            sT[(nb + 0) * 132 + mb + g + 8] = acc[mf][nf][2];
            sT[(nb + 1) * 132 + mb + g + 8] = acc[mf][nf][3];
        }
    }
    __syncthreads();
#pragma unroll
    for (int l = 0; l < 4; l++) {
        int f    = tid + l * 256;     // 0..1023
        int hrow = f >> 5;            // 0..31
        int seg  = f & 31;            // m f4-seg
        float4 v = *reinterpret_cast<float4*>(&sT[hrow * 132 + seg * 4]);
        *reinterpret_cast<float4*>(
            &g_curT[(size_t)(h0 + hrow) * SEQ + s0 + seg * 4]) = v;
    }
}

// ---------------------------------------------------------------------------
// Kernel 3: two-phase LIF scan (R11 exact, validated). One block per unit,
// 256 threads. Phase A parallel table build; Phase B 1-lookup-per-window
// serial chain; fused output projection in last block.
// ---------------------------------------------------------------------------
#define SCAN_SMEM_FLOATS (3 * SEQ + 128)
#define SCAN_SMEM_BYTES  (SCAN_SMEM_FLOATS * 4)
#define FULLW 0xffffffffu

__global__ void __launch_bounds__(256, 1)
snn_scan_kernel(const float* __restrict__ W2, float* __restrict__ out) {
    extern __shared__ float ssm[];
    float*    sQ   = ssm;
    float*    sXR  = ssm + SEQ;
    unsigned* sTT  = reinterpret_cast<unsigned*>(ssm + 2 * SEQ);
    float*    sP31 = ssm + 3 * SEQ;
    __shared__ unsigned slast;

    const int h    = blockIdx.x;
    const int tid  = threadIdx.x;
    const int lane = tid & 31;
    const int warp = tid >> 5;

    const float dinv = exp2f((float)lane * LOG2_INV_D);   // d^{-lane}
    const float d31  = exp2f(-31.0f * LOG2_INV_D);        // d^31

    // ===== Phase A =====
#pragma unroll 1
    for (int win = warp; win < SEQ / 32; win += 8) {
        float c = g_curT[(size_t)h * SEQ + win * 32 + lane];
        float p = c * dinv;
#pragma unroll
        for (int off = 1; off < 32; off <<= 1) {
            float v = __shfl_up_sync(FULLW, p, off);
            if (lane >= off) p += v;
        }
        float Q  = p - dinv;
        float pv = __shfl_up_sync(FULLW, p, 1);
        float XR = (lane == 0) ? 0.f : pv;                // P_{lane-1}

        float M0 = Q;
        float M1 = fmaxf(M0, __shfl_down_sync(FULLW, M0, 1));
        float M2 = fmaxf(M1, __shfl_down_sync(FULLW, M1, 2));
        float M3 = fmaxf(M2, __shfl_down_sync(FULLW, M2, 4));
        float M4 = fmaxf(M3, __shfl_down_sync(FULLW, M3, 8));
        float M5 = fmaxf(M4, __shfl_down_sync(FULLW, M4, 16));

        const float X = XR;
        const bool exists = (M5 >= X);
        int pos = lane;
        {
            float mk;
            mk = __shfl_sync(FULLW, M4, pos & 31); if (mk < X) pos += 16;
            mk = __shfl_sync(FULLW, M3, pos & 31); if (mk < X) pos += 8;
            mk = __shfl_sync(FULLW, M2, pos & 31); if (mk < X) pos += 4;
            mk = __shfl_sync(FULLW, M1, pos & 31); if (mk < X) pos += 2;
            mk = __shfl_sync(FULLW, M0, pos & 31); if (mk < X) pos += 1;
        }
        unsigned st;
        if (!exists)         st = (2u << 5) | (unsigned)lane;
        else if (pos <= 28)  st = (1u << 7) | (0u << 5) | (unsigned)(pos + 3);
        else                 st = (1u << 7) | (1u << 5) | (unsigned)(pos - 29);

#pragma unroll
        for (int r = 0; r < 4; r++) {
            unsigned s2 = __shfl_sync(FULLW, st, st & 31);
            if (((st >> 5) & 3u) == 0u)
                st = (((st >> 7) + (s2 >> 7)) << 7) | (s2 & 0x7Fu);
        }

        sQ [win * 32 + lane] = Q;
        sXR[win * 32 + lane] = XR;
        sTT[win * 32 + lane] = st;
        if (lane == 31) sP31[win] = p;
    }
    __syncthreads();

    // ===== Phase B (warp 0) =====
    if (warp == 0) {
        int   isCarry = 1, o = 0, cnt = 0;
        float X = 0.f;
#pragma unroll 1
        for (int win = 0; win < SEQ / 32; win++) {
            float    Qv  = sQ [win * 32 + lane];
            float    XRv = sXR[win * 32 + lane];
            unsigned Tv  = sTT[win * 32 + lane];
            float    P31 = sP31[win];

            unsigned st;
            if (isCarry) {
                st = __shfl_sync(FULLW, Tv, o);
            } else {
                unsigned ball = __ballot_sync(FULLW, Qv >= X);
                if (!ball) { X = -DECAYF * (d31 * (P31 - X)); continue; }
                int t1 = __ffs(ball) - 1;
                cnt++;
                if (t1 >= 29) { isCarry = 1; o = t1 - 29; continue; }
                st = __shfl_sync(FULLW, Tv, t1 + 3);
            }
            cnt += (int)(st >> 7);
            unsigned term = (st >> 5) & 3u;
            unsigned p5   = st & 31u;
            float xr = __shfl_sync(FULLW, XRv, p5);
            if (term == 1u) { isCarry = 1; o = (int)p5; }
            else            { isCarry = 0; X = -DECAYF * (d31 * (P31 - xr)); }
        }
        if (lane == 0) g_cnt[h] = (float)cnt;
    }
    __syncthreads();
    __threadfence();
    if (tid == 0) slast = atomicAdd(&g_done, 1u);
    __syncthreads();

    if (slast == HID - 1 && tid < OUTD) {
        __threadfence();
        volatile float* vc = g_cnt;
        float a = 0.f;
#pragma unroll 16
        for (int k = 0; k < HID; k++)
            a += vc[k] * W2[(size_t)k * OUTD + tid];
        a *= (1.0f / (float)SEQ);
#pragma unroll
        for (int b = 0; b < BATCH; b++)
            out[(size_t)b * OUTD + tid] = a;
        __threadfence();
        if (tid == 0) g_done = 0;
    }
}

// ---------------------------------------------------------------------------
extern "C" void kernel_launch(void* const* d_in, const int* in_sizes, int n_in,
                              void* d_out, int out_size) {
    const float* x  = (const float*)d_in[0];   // [32][4096][512]
    const float* w1 = (const float*)d_in[1];   // [512][256]
    const float* w2 = (const float*)d_in[2];   // [256][128]
    float* out = (float*)d_out;                // [32][128]

    cudaFuncSetAttribute(snn_mma_kernel,
                         cudaFuncAttributeMaxDynamicSharedMemorySize,
                         MMA_SMEM_BYTES);
    cudaFuncSetAttribute(snn_scan_kernel,
                         cudaFuncAttributeMaxDynamicSharedMemorySize,
                         SCAN_SMEM_BYTES);

    snn_wprep_kernel<<<EMBED, HID>>>(w1);
    snn_mean_kernel<<<SEQ * EMBED / 4 / 256, 256>>>(x);
    snn_mma_kernel<<<dim3(SEQ / MT, HID / NT), 256, MMA_SMEM_BYTES>>>();
    snn_scan_kernel<<<HID, 256, SCAN_SMEM_BYTES>>>(w2, out);
}

// round 14
// speedup vs baseline: 1.1393x; 1.0948x over previous
#include <cuda_runtime.h>
#include <cuda_bf16.h>
#include <cstdint>

#define BATCH 32
#define SEQ   4096
#define EMBED 512
#define HID   256
#define OUTD  128
#define DECAYF 0.95f
#define LOG2_INV_D 0.07400058144377693f   // log2(1/0.95)

#define KSPLIT (3 * EMBED)                // 1536: A = (hi | hi | lo)

__device__ __nv_bfloat16 g_a3[SEQ * KSPLIT];    // A split   [4096][1536]
__device__ __nv_bfloat16 g_w1t[HID * KSPLIT];   // W1^T split [256][1536]: (hi|lo|hi)
__device__ float    g_curT[HID * SEQ];          // currents TRANSPOSED [256][4096]
__device__ float    g_cnt[HID];
__device__ unsigned g_done;

// ---------------------------------------------------------------------------
// Kernel 1: batch mean (emits split-bf16 A3) + fused W1 split prep (R11 exact).
// ---------------------------------------------------------------------------
__global__ void snn_mean_kernel(const float* __restrict__ x,
                                const float* __restrict__ W1) {
    if (blockIdx.x >= 2048) {                 // --- wprep part ---
        const int k = blockIdx.x - 2048;      // 0..511
        const int n = threadIdx.x;            // 0..255
        float v = W1[(size_t)k * HID + n];
        __nv_bfloat16 hi = __float2bfloat16(v);
        __nv_bfloat16 lo = __float2bfloat16(v - __bfloat162float(hi));
        g_w1t[(size_t)n * KSPLIT + k]             = hi;
        g_w1t[(size_t)n * KSPLIT + EMBED + k]     = lo;
        g_w1t[(size_t)n * KSPLIT + 2 * EMBED + k] = hi;
        return;
    }
    const int NF4 = (SEQ * EMBED) / 4;
    int i = blockIdx.x * blockDim.x + threadIdx.x;
    if (i >= NF4) return;
    const float4* x4 = reinterpret_cast<const float4*>(x);
    float sx = 0.f, sy = 0.f, sz = 0.f, sw = 0.f;
#pragma unroll
    for (int b = 0; b < BATCH; b++) {
        float4 v = x4[(size_t)b * NF4 + i];
        sx += v.x; sy += v.y; sz += v.z; sw += v.w;
    }
    const float inv = 1.0f / 32.0f;
    float v0 = sx * inv, v1 = sy * inv, v2 = sz * inv, v3 = sw * inv;

    __nv_bfloat16 h0 = __float2bfloat16(v0), h1 = __float2bfloat16(v1);
    __nv_bfloat16 h2 = __float2bfloat16(v2), h3 = __float2bfloat16(v3);
    __nv_bfloat16 l0 = __float2bfloat16(v0 - __bfloat162float(h0));
    __nv_bfloat16 l1 = __float2bfloat16(v1 - __bfloat162float(h1));
    __nv_bfloat16 l2 = __float2bfloat16(v2 - __bfloat162float(h2));
    __nv_bfloat16 l3 = __float2bfloat16(v3 - __bfloat162float(h3));

    __nv_bfloat162 ha = {h0, h1}, hb = {h2, h3};
    __nv_bfloat162 la = {l0, l1}, lb = {l2, l3};
    uint2 hu, lu;
    hu.x = *reinterpret_cast<unsigned*>(&ha); hu.y = *reinterpret_cast<unsigned*>(&hb);
    lu.x = *reinterpret_cast<unsigned*>(&la); lu.y = *reinterpret_cast<unsigned*>(&lb);

    const int s = i >> 7, d4 = i & 127;
    const size_t base = (size_t)s * KSPLIT + d4 * 4;
    *reinterpret_cast<uint2*>(&g_a3[base])             = hu;
    *reinterpret_cast<uint2*>(&g_a3[base + EMBED])     = hu;
    *reinterpret_cast<uint2*>(&g_a3[base + 2 * EMBED]) = lu;
}

// ---------------------------------------------------------------------------
// Kernel 2: HMMA bf16 GEMM (R11 exact: MT=128, NT=64, grid (32,4), 8 warps
// 4m x 2n, cp.async double-buffered, wait_group 1).
// ---------------------------------------------------------------------------
#define MT 128
#define NT 64
#define KCH 64
#define NCH (KSPLIT / KCH)        // 24
#define APIT 72
#define SA_BYTES (MT * APIT * 2)  // 18432
#define SB_BYTES (NT * APIT * 2)  // 9216
#define SMB_OFF 36864
#define MMA_SMEM_BYTES 55296

__device__ __forceinline__ void cp16(unsigned dst, const void* src) {
    asm volatile("cp.async.cg.shared.global [%0], [%1], 16;" :: "r"(dst), "l"(src));
}
#define CP_COMMIT() asm volatile("cp.async.commit_group;")
#define CP_WAIT1()  asm volatile("cp.async.wait_group 1;")
#define CP_WAIT0()  asm volatile("cp.async.wait_group 0;")

__device__ __forceinline__ void mma16816(float& d0, float& d1, float& d2, float& d3,
                                         uint32_t a0, uint32_t a1, uint32_t a2, uint32_t a3,
                                         uint32_t b0, uint32_t b1) {
    asm volatile(
        "mma.sync.aligned.m16n8k16.row.col.f32.bf16.bf16.f32 "
        "{%0,%1,%2,%3}, {%4,%5,%6,%7}, {%8,%9}, {%0,%1,%2,%3};"
        : "+f"(d0), "+f"(d1), "+f"(d2), "+f"(d3)
        : "r"(a0), "r"(a1), "r"(a2), "r"(a3), "r"(b0), "r"(b1));
}

__global__ void __launch_bounds__(256, 1)
snn_mma_kernel(void) {
    extern __shared__ char smem[];
    const unsigned sb = (unsigned)__cvta_generic_to_shared(smem);
    __nv_bfloat16* sm16 = reinterpret_cast<__nv_bfloat16*>(smem);

    const int tid  = threadIdx.x;
    const int wid  = tid >> 5;
    const int lane = tid & 31;
    const int g = lane >> 2;
    const int t = lane & 3;
    const int warp_m = wid >> 1;
    const int warp_n = wid & 1;
    const int s0 = blockIdx.x * MT;
    const int h0 = blockIdx.y * NT;

    auto load_chunk = [&](int c, int buf) {
        const __nv_bfloat16* As = &g_a3[(size_t)s0 * KSPLIT + c * KCH];
        unsigned dA = sb + buf * SA_BYTES;
#pragma unroll
        for (int l = 0; l < 4; l++) {
            int f = tid + l * 256;
            int r = f >> 3, sg = f & 7;
            cp16(dA + r * (APIT * 2) + sg * 16, As + (size_t)r * KSPLIT + sg * 8);
        }
        const __nv_bfloat16* Bs = &g_w1t[(size_t)h0 * KSPLIT + c * KCH];
        unsigned dB = sb + SMB_OFF + buf * SB_BYTES;
#pragma unroll
        for (int l = 0; l < 2; l++) {
            int f = tid + l * 256;
            int r = f >> 3, sg = f & 7;
            cp16(dB + r * (APIT * 2) + sg * 16, Bs + (size_t)r * KSPLIT + sg * 8);
        }
        CP_COMMIT();
    };

    float acc[2][4][4];
#pragma unroll
    for (int i = 0; i < 2; i++)
#pragma unroll
        for (int j = 0; j < 4; j++)
#pragma unroll
            for (int r = 0; r < 4; r++) acc[i][j][r] = 0.f;

    load_chunk(0, 0);
    load_chunk(1, 1);

#pragma unroll 1
    for (int c = 0; c < NCH; c++) {
        if (c + 1 < NCH) CP_WAIT1(); else CP_WAIT0();
        __syncthreads();

        const int buf = c & 1;
        const __nv_bfloat16* A = sm16 + buf * (SA_BYTES / 2);
        const __nv_bfloat16* B = sm16 + (SMB_OFF / 2) + buf * (SB_BYTES / 2);

#pragma unroll
        for (int ks = 0; ks < KCH / 16; ks++) {
            const int kb = ks * 16;
            uint32_t af[2][4];
#pragma unroll
            for (int mf = 0; mf < 2; mf++) {
                const int rb = warp_m * 32 + mf * 16;
                af[mf][0] = *reinterpret_cast<const uint32_t*>(&A[(rb + g)     * APIT + kb + t * 2]);
                af[mf][1] = *reinterpret_cast<const uint32_t*>(&A[(rb + g + 8) * APIT + kb + t * 2]);
                af[mf][2] = *reinterpret_cast<const uint32_t*>(&A[(rb + g)     * APIT + kb + t * 2 + 8]);
                af[mf][3] = *reinterpret_cast<const uint32_t*>(&A[(rb + g + 8) * APIT + kb + t * 2 + 8]);
            }
            uint32_t bf[4][2];
#pragma unroll
            for (int nf = 0; nf < 4; nf++) {
                const int nr = warp_n * 32 + nf * 8 + g;
                bf[nf][0] = *reinterpret_cast<const uint32_t*>(&B[nr * APIT + kb + t * 2]);
                bf[nf][1] = *reinterpret_cast<const uint32_t*>(&B[nr * APIT + kb + t * 2 + 8]);
            }
#pragma unroll
            for (int mf = 0; mf < 2; mf++)
#pragma unroll
                for (int nf = 0; nf < 4; nf++)
                    mma16816(acc[mf][nf][0], acc[mf][nf][1], acc[mf][nf][2], acc[mf][nf][3],
                             af[mf][0], af[mf][1], af[mf][2], af[mf][3],
                             bf[nf][0], bf[nf][1]);
        }
        __syncthreads();
        if (c + 2 < NCH) load_chunk(c + 2, buf);
    }

    float* sT = reinterpret_cast<float*>(smem);   // [64][132]
#pragma unroll
    for (int mf = 0; mf < 2; mf++) {
        const int mb = warp_m * 32 + mf * 16;
#pragma unroll
        for (int nf = 0; nf < 4; nf++) {
            const int nb = warp_n * 32 + nf * 8 + t * 2;
            sT[(nb + 0) * 132 + mb + g]     = acc[mf][nf][0];
            sT[(nb + 1) * 132 + mb + g]     = acc[mf][nf][1];
            sT[(nb + 0) * 132 + mb + g + 8] = acc[mf][nf][2];
            sT[(nb + 1) * 132 + mb + g + 8] = acc[mf][nf][3];
        }
    }
    __syncthreads();
#pragma unroll
    for (int l = 0; l < 8; l++) {
        int f    = tid + l * 256;
        int hrow = f >> 5;
        int seg  = f & 31;
        float4 v = *reinterpret_cast<float4*>(&sT[hrow * 132 + seg * 4]);
        *reinterpret_cast<float4*>(
            &g_curT[(size_t)(h0 + hrow) * SEQ + s0 + seg * 4]) = v;
    }
}

// ---------------------------------------------------------------------------
// Kernel 3: two-phase LIF scan with PRECOMPOSED EXITS.
// Phase A (8 warps x 16 windows): prefix P/Q, skip-max descent, pointer
// doubling, then compose per-restart-lane exit records:
//   meta = (count<<4) | (isCarryExit<<2) | o      (o in 0..2 for carry)
//   Xn   = -d * (d31 * (P31 - XR[p5]))            (CONT exit threshold)
//   sC1[win] = -d * d31 * P31  (no-spike propagation constant)
// Phase B (warp 0): per window ONE ballot + ONE pair of parallel shfls,
// registers prefetched one window ahead. Same algebra as validated R11.
// ---------------------------------------------------------------------------
#define SCAN_SMEM_FLOATS (3 * SEQ + 128)
#define SCAN_SMEM_BYTES  (SCAN_SMEM_FLOATS * 4)
#define FULLW 0xffffffffu

__global__ void __launch_bounds__(256, 1)
snn_scan_kernel(const float* __restrict__ W2, float* __restrict__ out) {
    extern __shared__ float ssm[];
    float*    sQ   = ssm;                                   // [4096]
    unsigned* sMt  = reinterpret_cast<unsigned*>(ssm + SEQ);// [4096]
    float*    sXn  = ssm + 2 * SEQ;                         // [4096]
    float*    sC1  = ssm + 3 * SEQ;                         // [128]
    __shared__ unsigned slast;

    const int h    = blockIdx.x;
    const int tid  = threadIdx.x;
    const int lane = tid & 31;
    const int warp = tid >> 5;

    const float dinv = exp2f((float)lane * LOG2_INV_D);   // d^{-lane}
    const float d31  = exp2f(-31.0f * LOG2_INV_D);        // d^31
    const float C2   = DECAYF * d31;                      // no-spike X multiplier

    // ===== Phase A =====
#pragma unroll 1
    for (int win = warp; win < SEQ / 32; win += 8) {
        float c = g_curT[(size_t)h * SEQ + win * 32 + lane];
        float p = c * dinv;
#pragma unroll
        for (int off = 1; off < 32; off <<= 1) {
            float v = __shfl_up_sync(FULLW, p, off);
            if (lane >= off) p += v;
        }
        float Q  = p - dinv;
        float pv = __shfl_up_sync(FULLW, p, 1);
        float XR = (lane == 0) ? 0.f : pv;                // P_{lane-1}

        float M0 = Q;
        float M1 = fmaxf(M0, __shfl_down_sync(FULLW, M0, 1));
        float M2 = fmaxf(M1, __shfl_down_sync(FULLW, M1, 2));
        float M3 = fmaxf(M2, __shfl_down_sync(FULLW, M2, 4));
        float M4 = fmaxf(M3, __shfl_down_sync(FULLW, M3, 8));
        float M5 = fmaxf(M4, __shfl_down_sync(FULLW, M4, 16));

        const float X = XR;
        const bool exists = (M5 >= X);
        int pos = lane;
        {
            float mk;
            mk = __shfl_sync(FULLW, M4, pos & 31); if (mk < X) pos += 16;
            mk = __shfl_sync(FULLW, M3, pos & 31); if (mk < X) pos += 8;
            mk = __shfl_sync(FULLW, M2, pos & 31); if (mk < X) pos += 4;
            mk = __shfl_sync(FULLW, M1, pos & 31); if (mk < X) pos += 2;
            mk = __shfl_sync(FULLW, M0, pos & 31); if (mk < X) pos += 1;
        }
        unsigned st;
        if (!exists)         st = (2u << 5) | (unsigned)lane;
        else if (pos <= 28)  st = (1u << 7) | (0u << 5) | (unsigned)(pos + 3);
        else                 st = (1u << 7) | (1u << 5) | (unsigned)(pos - 29);

#pragma unroll
        for (int r = 0; r < 4; r++) {
            unsigned s2 = __shfl_sync(FULLW, st, st & 31);
            if (((st >> 5) & 3u) == 0u)
                st = (((st >> 7) + (s2 >> 7)) << 7) | (s2 & 0x7Fu);
        }

        // compose exit record
        const unsigned cntw = st >> 7;
        const unsigned term = (st >> 5) & 3u;
        const unsigned p5   = st & 31u;
        const float P31 = __shfl_sync(FULLW, p, 31);
        const float xr  = __shfl_sync(FULLW, XR, p5);
        const float Xn  = -DECAYF * (d31 * (P31 - xr));
        unsigned meta;
        if (term == 1u) meta = (cntw << 4) | (1u << 2) | p5;   // carry exit
        else            meta = (cntw << 4);                     // CONT exit

        sQ [win * 32 + lane] = Q;
        sMt[win * 32 + lane] = meta;
        sXn[win * 32 + lane] = Xn;
        if (lane == 31) sC1[win] = -DECAYF * d31 * p;           // -d*d31*P31
    }
    __syncthreads();

    // ===== Phase B (warp 0): prefetched single-lookup chain =====
    if (warp == 0) {
        int   isCarry = 1, o = 0, cnt = 0;
        float X = 0.f;
        float    qc = sQ [lane];
        unsigned mc = sMt[lane];
        float    xc = sXn[lane];
#pragma unroll 1
        for (int win = 0; win < SEQ / 32; win++) {
            float qn = 0.f, xn2 = 0.f;
            unsigned mn = 0u;
            if (win + 1 < SEQ / 32) {
                qn  = sQ [(win + 1) * 32 + lane];
                mn  = sMt[(win + 1) * 32 + lane];
                xn2 = sXn[(win + 1) * 32 + lane];
            }

            if (isCarry) {
                unsigned m = __shfl_sync(FULLW, mc, o);
                float    x = __shfl_sync(FULLW, xc, o);
                cnt += (int)(m >> 4);
                if (m & 4u) { isCarry = 1; o = (int)(m & 3u); }
                else        { isCarry = 0; X = x; }
            } else {
                unsigned ball = __ballot_sync(FULLW, qc >= X);
                if (ball) {
                    int t1 = __ffs(ball) - 1;
                    cnt++;
                    if (t1 >= 29) { isCarry = 1; o = t1 - 29; }
                    else {
                        unsigned m = __shfl_sync(FULLW, mc, t1 + 3);
                        float    x = __shfl_sync(FULLW, xc, t1 + 3);
                        cnt += (int)(m >> 4);
                        if (m & 4u) { isCarry = 1; o = (int)(m & 3u); }
                        else        { isCarry = 0; X = x; }
                    }
                } else {
                    X = fmaf(C2, X, sC1[win]);
                }
            }
            qc = qn; mc = mn; xc = xn2;
        }
        if (lane == 0) g_cnt[h] = (float)cnt;
    }
    __syncthreads();
    __threadfence();
    if (tid == 0) slast = atomicAdd(&g_done, 1u);
    __syncthreads();

    if (slast == HID - 1 && tid < OUTD) {
        __threadfence();
        volatile float* vc = g_cnt;
        float a = 0.f;
#pragma unroll 16
        for (int k = 0; k < HID; k++)
            a += vc[k] * W2[(size_t)k * OUTD + tid];
        a *= (1.0f / (float)SEQ);
#pragma unroll
        for (int b = 0; b < BATCH; b++)
            out[(size_t)b * OUTD + tid] = a;
        __threadfence();
        if (tid == 0) g_done = 0;
    }
}

// ---------------------------------------------------------------------------
extern "C" void kernel_launch(void* const* d_in, const int* in_sizes, int n_in,
                              void* d_out, int out_size) {
    const float* x  = (const float*)d_in[0];   // [32][4096][512]
    const float* w1 = (const float*)d_in[1];   // [512][256]
    const float* w2 = (const float*)d_in[2];   // [256][128]
    float* out = (float*)d_out;                // [32][128]

    cudaFuncSetAttribute(snn_mma_kernel,
                         cudaFuncAttributeMaxDynamicSharedMemorySize,
                         MMA_SMEM_BYTES);
    cudaFuncSetAttribute(snn_scan_kernel,
                         cudaFuncAttributeMaxDynamicSharedMemorySize,
                         SCAN_SMEM_BYTES);

    snn_mean_kernel<<<2048 + EMBED, 256>>>(x, w1);
    snn_mma_kernel<<<dim3(SEQ / MT, HID / NT), 256, MMA_SMEM_BYTES>>>();
    snn_scan_kernel<<<HID, 256, SCAN_SMEM_BYTES>>>(w2, out);
}